// round 17
// baseline (speedup 1.0000x reference)
#include <cuda_runtime.h>
#include <cuda_bf16.h>
#include <cstdint>

// Problem constants (fixed by the dataset)
#define BATCH   256
#define PASTN   512
#define HID     512
#define FUT     64
#define TOTT    576          // PASTN + FUT
#define NCTA    128          // 2 batch-halves x 64 gate-tiles
#define NTHR    256          // 8 warps
#define GRPC    64           // CTAs per inter-CTA barrier group (one batch-half)
#define MT      128          // batches per half
#define KCH     128          // K chunk
#define NCHUNK  4

// ---------------- device globals (scratch; no allocation allowed) -----------
__device__ __nv_bfloat16 g_hhi[2][BATCH][HID];   // h high bf16, double buffered
__device__ __nv_bfloat16 g_hlo[2][BATCH][HID];   // h low  bf16
__device__ float g_xT[PASTN * BATCH];            // transposed input [t][b]
__device__ __align__(128) unsigned g_arrive[2 * 32];
__device__ __align__(128) unsigned g_release[2 * 32];
__device__ unsigned g_garrive;
__device__ unsigned g_grelease;

// ---------------- helpers ---------------------------------------------------
__device__ __forceinline__ unsigned packbf(float lo, float hi) {
    unsigned r;  // d.hi = first asm src, d.lo = second
    asm("cvt.rn.bf16x2.f32 %0, %1, %2;" : "=r"(r) : "f"(hi), "f"(lo));
    return r;
}
__device__ __forceinline__ float bf16rt(float x) {
    return __bfloat162float(__float2bfloat16(x));
}
__device__ __forceinline__ float sigf(float x) { return 1.0f / (1.0f + __expf(-x)); }

// warp-level bf16 MMA m16n8k16 (HMMA fallback path on sm_103)
__device__ __forceinline__ void mma16816(float *d, uint32_t a0, uint32_t a1,
                                         uint32_t a2, uint32_t a3,
                                         uint32_t b0, uint32_t b1) {
    asm volatile(
        "mma.sync.aligned.m16n8k16.row.col.f32.bf16.bf16.f32 "
        "{%0,%1,%2,%3}, {%4,%5,%6,%7}, {%8,%9}, {%0,%1,%2,%3};"
        : "+f"(d[0]), "+f"(d[1]), "+f"(d[2]), "+f"(d[3])
        : "r"(a0), "r"(a1), "r"(a2), "r"(a3), "r"(b0), "r"(b1));
}

// inter-CTA barrier core (one thread). gpu-scope fences order stores and
// (sm_103a) invalidate L1D so post-barrier h LDGs are fresh.
__device__ __forceinline__ void barrier_core(int grp, unsigned target) {
    __threadfence();
    unsigned prev = atomicAdd(&g_arrive[grp], 1u);
    if (prev == GRPC - 1) {
        g_arrive[grp] = 0;
        __threadfence();
        *((volatile unsigned *)&g_release[grp]) = target;
    } else {
        while ((int)(*((volatile unsigned *)&g_release[grp]) - target) < 0) { }
    }
    __threadfence();
}
__device__ __forceinline__ void global_barrier_core(unsigned target) {
    __threadfence();
    unsigned prev = atomicAdd(&g_garrive, 1u);
    if (prev == NCTA - 1) {
        g_garrive = 0;
        __threadfence();
        *((volatile unsigned *)&g_grelease) = target;
    } else {
        while ((int)(*((volatile unsigned *)&g_grelease) - target) < 0) { }
    }
    __threadfence();
}

// dynamic smem plan (bytes):
//   [0, 65536)        B fragments: [nt][ks][lane] x {bhi0,bhi1,blo0,blo1}
//   [65536, +65536)   A buffer 0: hi 32KB | lo 32KB  (fragment-direct, swizzled)
//   [131072, +65536)  A buffer 1: hi | lo
#define SMEM_BYTES (65536 + 2 * 65536)

extern __shared__ char dynsm[];

__global__ void __launch_bounds__(NTHR, 1)
lstm_mma_kernel(const float *__restrict__ xin,    // [256][512][1]
                const float *__restrict__ Wih,    // [2048][1]
                const float *__restrict__ Whh,    // [2048][512]
                const float *__restrict__ bih,    // [2048]
                const float *__restrict__ bhh,    // [2048]
                const float *__restrict__ Wdec,   // [1][512]
                const float *__restrict__ bdec,   // [1]
                float *__restrict__ out)          // [256][576][1]
{
    __shared__ float wih_s[8][4];    // [unit][gate i,f,g,o]
    __shared__ float bsum_s[8][4];
    __shared__ unsigned s_ep, s_gep;

    const int tid = threadIdx.x;
    const int bh  = blockIdx.x & 1;            // batch half
    const int jt  = blockIdx.x >> 1;           // gate tile (8 units)
    const int w   = tid >> 5;                  // warp 0..7 -> rows 16w..16w+15
    const int l   = tid & 31;
    const int r0  = l >> 2;                    // fragment row group
    const int s   = l & 3;                     // fragment col group
    const int grp = bh * 32;

    // producer role: one (row, k-half) per thread
    const int prow = tid >> 1;                 // 0..127
    const int pkh  = tid & 1;
    const int pmt  = prow >> 4;
    const int prl  = prow & 15;
    const int pq1  = prl >> 3;
    const int plh  = prl & 7;

    uint32_t *Bfr = (uint32_t *)dynsm;

    // ---- prologue: W_hh bf16 hi/lo fragments ------------------------------
    // slot = ((nt*32+ks)*32+lane)*4 + pl*2 + rq
    for (int it = tid; it < 16384; it += NTHR) {
        int rq = it & 1, pl = (it >> 1) & 1, lane = (it >> 2) & 31;
        int ks = (it >> 7) & 31, nt = it >> 12;
        int n = nt * 8 + (lane >> 2);
        int k = ks * 16 + (lane & 3) * 2 + 8 * rq;
        int uu = n >> 2, g = n & 3;
        float2 v = *(const float2 *)(Whh + (size_t)(g * HID + jt * 8 + uu) * HID + k);
        float h0 = bf16rt(v.x), h1 = bf16rt(v.y);
        Bfr[it] = (pl == 0) ? packbf(h0, h1) : packbf(v.x - h0, v.y - h1);
    }
    if (tid < 32) {
        int uu = tid >> 2, g = tid & 3;
        int j = g * HID + jt * 8 + uu;
        bsum_s[uu][g] = bih[j] + bhh[j];
        wih_s[uu][g]  = Wih[j];                // FEAT = 1
    }
    float wd[8];
#pragma unroll
    for (int u = 0; u < 8; ++u) wd[u] = Wdec[jt * 8 + u];
    const float bdec_v = bdec[0];

    for (int i = blockIdx.x * NTHR + tid; i < PASTN * BATCH; i += NCTA * NTHR) {
        int t = i >> 8, b = i & (BATCH - 1);
        g_xT[i] = xin[b * PASTN + t];
    }
    for (int i = jt * NTHR + tid; i < MT * TOTT; i += 64 * NTHR) {
        int bl = i / TOTT, tt = i - bl * TOTT;
        out[(bh * MT + bl) * TOTT + tt] = bdec_v;
    }
    {   // h0 = 0.01 (CTA x fills rows 2x, 2x+1)
        __nv_bfloat16 hhi = __float2bfloat16(0.01f);
        __nv_bfloat16 hlo = __float2bfloat16(0.01f - bf16rt(0.01f));
        for (int i = tid; i < 2 * HID; i += NTHR) {
            int b = blockIdx.x * 2 + (i >> 9), k = i & (HID - 1);
            g_hhi[0][b][k] = hhi;
            g_hlo[0][b][k] = hlo;
        }
    }
    if (tid == 0) {
        s_gep = *((volatile unsigned *)&g_grelease);
        s_ep  = *((volatile unsigned *)&g_release[grp]);
    }
    __syncthreads();
    if (tid == 0) global_barrier_core(s_gep + 1);
    __syncthreads();

    unsigned epoch = s_ep;
    float cst[4] = {0.01f, 0.01f, 0.01f, 0.01f};
    int p = 0;
    const int rowx = bh * MT + w * 16 + r0 + 8 * (l & 1);

    for (int t = 0; t < TOTT; ++t) {
        float xr = (t < PASTN) ? g_xT[t * BATCH + rowx]
                               : out[rowx * TOTT + (t - 1)];

        float acc[4][4];
#pragma unroll
        for (int nt = 0; nt < 4; ++nt)
#pragma unroll
            for (int q = 0; q < 4; ++q) acc[nt][q] = 0.0f;

        // ---- stage chunk 0 into buffer 0 ----------------------------------
        {
            const uint4 *sh = (const uint4 *)&g_hhi[p][bh * MT + prow][pkh * 64];
            const uint4 *sl = (const uint4 *)&g_hlo[p][bh * MT + prow][pkh * 64];
            uint32_t *Ah = (uint32_t *)(dynsm + 65536);
            uint32_t *Al = Ah + 8192;
#pragma unroll
            for (int j = 0; j < 8; ++j) {
                uint4 vh = sh[j], vl = sl[j];
                int ks = pkh * 4 + (j >> 1), q = (j & 1) * 2 + pq1;
                int ib = ((pmt * 8 + ks) * 32 + plh * 4) * 4 + q;
                int x0 = (ib + 0)  ^ ((((ib + 0)  >> 5) & 3) << 2);
                int x1 = (ib + 4)  ^ ((((ib + 4)  >> 5) & 3) << 2);
                int x2 = (ib + 8)  ^ ((((ib + 8)  >> 5) & 3) << 2);
                int x3 = (ib + 12) ^ ((((ib + 12) >> 5) & 3) << 2);
                Ah[x0] = vh.x; Ah[x1] = vh.y; Ah[x2] = vh.z; Ah[x3] = vh.w;
                Al[x0] = vl.x; Al[x1] = vl.y; Al[x2] = vl.z; Al[x3] = vl.w;
            }
        }
        __syncthreads();

        for (int c = 0; c < NCHUNK; ++c) {
            uint4 th[8], tl[8];
            if (c < 3) {
                const uint4 *sh = (const uint4 *)
                    &g_hhi[p][bh * MT + prow][(c + 1) * KCH + pkh * 64];
                const uint4 *sl = (const uint4 *)
                    &g_hlo[p][bh * MT + prow][(c + 1) * KCH + pkh * 64];
#pragma unroll
                for (int j = 0; j < 8; ++j) { th[j] = sh[j]; tl[j] = sl[j]; }
            }

            // ---- consume chunk c ------------------------------------------
            const uint4 *Ahi = (const uint4 *)(dynsm + 65536 + (c & 1) * 65536);
            const uint4 *Alo = Ahi + 2048;
            const uint4 *Bf4 = (const uint4 *)dynsm;
#pragma unroll
            for (int ks = 0; ks < 8; ++ks) {
                int unit = ((w * 8 + ks) * 32 + l) ^ ((l >> 3) & 3);
                uint4 ah = Ahi[unit];
                uint4 al = Alo[unit];
#pragma unroll
                for (int nt = 0; nt < 4; ++nt) {
                    uint4 bb = Bf4[(nt * 32 + c * 8 + ks) * 32 + l];
                    mma16816(acc[nt], ah.x, ah.y, ah.z, ah.w, bb.x, bb.y);
                    mma16816(acc[nt], ah.x, ah.y, ah.z, ah.w, bb.z, bb.w);
                    mma16816(acc[nt], al.x, al.y, al.z, al.w, bb.x, bb.y);
                }
            }

            if (c < 3) {
                uint32_t *Ah = (uint32_t *)(dynsm + 65536 + ((c + 1) & 1) * 65536);
                uint32_t *Al = Ah + 8192;
#pragma unroll
                for (int j = 0; j < 8; ++j) {
                    int ks = pkh * 4 + (j >> 1), q = (j & 1) * 2 + pq1;
                    int ib = ((pmt * 8 + ks) * 32 + plh * 4) * 4 + q;
                    int x0 = (ib + 0)  ^ ((((ib + 0)  >> 5) & 3) << 2);
                    int x1 = (ib + 4)  ^ ((((ib + 4)  >> 5) & 3) << 2);
                    int x2 = (ib + 8)  ^ ((((ib + 8)  >> 5) & 3) << 2);
                    int x3 = (ib + 12) ^ ((((ib + 12) >> 5) & 3) << 2);
                    Ah[x0] = th[j].x; Ah[x1] = th[j].y; Ah[x2] = th[j].z; Ah[x3] = th[j].w;
                    Al[x0] = tl[j].x; Al[x1] = tl[j].y; Al[x2] = tl[j].z; Al[x3] = tl[j].w;
                }
            }
            __syncthreads();
        }

        // ---- epilogue: gates -> cells (shfl exchange), publish h, decode ---
        float hval[4];
#pragma unroll
        for (int nt = 0; nt < 4; ++nt) {
            float sendA = (s & 1) ? acc[nt][0] : acc[nt][2];
            float sendB = (s & 1) ? acc[nt][1] : acc[nt][3];
            float rA = __shfl_xor_sync(0xffffffffu, sendA, 1);
            float rB = __shfl_xor_sync(0xffffffffu, sendB, 1);
            float gi = (s & 1) ? rA : acc[nt][0];
            float gf = (s & 1) ? rB : acc[nt][1];
            float gg = (s & 1) ? acc[nt][2] : rA;
            float go = (s & 1) ? acc[nt][3] : rB;
            int uu = 2 * nt + (s >> 1);
            float4 w4 = *(const float4 *)wih_s[uu];
            float4 b4 = *(const float4 *)bsum_s[uu];
            gi += xr * w4.x + b4.x;
            gf += xr * w4.y + b4.y;
            gg += xr * w4.z + b4.z;
            go += xr * w4.w + b4.w;
            cst[nt] = sigf(gf) * cst[nt] + sigf(gi) * tanhf(gg);
            hval[nt] = sigf(go) * tanhf(cst[nt]);
        }

        const int p1 = p ^ 1;
        uint32_t hi4[4], lo4[4];
        float y = 0.0f;
#pragma unroll
        for (int nt = 0; nt < 4; ++nt) {
            float hr = __shfl_xor_sync(0xffffffffu, hval[nt], 2);
            float he = (s < 2) ? hval[nt] : hr;    // unit 2nt
            float ho = (s < 2) ? hr : hval[nt];    // unit 2nt+1
            float eh = bf16rt(he), oh = bf16rt(ho);
            hi4[nt] = packbf(eh, oh);
            lo4[nt] = packbf(he - eh, ho - oh);
            y += he * wd[2 * nt] + ho * wd[2 * nt + 1];
        }
        if (s < 2) {
            int row = bh * MT + w * 16 + r0 + 8 * s;
            *(uint4 *)&g_hhi[p1][row][jt * 8] = make_uint4(hi4[0], hi4[1], hi4[2], hi4[3]);
            *(uint4 *)&g_hlo[p1][row][jt * 8] = make_uint4(lo4[0], lo4[1], lo4[2], lo4[3]);
            atomicAdd(&out[row * TOTT + t], y);    // REDG
        }

        ++epoch;
        __syncthreads();
        if (tid == 0) barrier_core(grp, epoch);
        __syncthreads();
        p = p1;
    }
}

// ---------------- launch -----------------------------------------------------
extern "C" void kernel_launch(void *const *d_in, const int *in_sizes, int n_in,
                              void *d_out, int out_size) {
    const float *xin  = (const float *)d_in[0];
    const float *Wih  = (const float *)d_in[2];
    const float *Whh  = (const float *)d_in[3];
    const float *bih  = (const float *)d_in[4];
    const float *bhh  = (const float *)d_in[5];
    const float *Wdec = (const float *)d_in[6];
    const float *bdec = (const float *)d_in[7];
    float *out = (float *)d_out;

    cudaFuncSetAttribute(lstm_mma_kernel,
                         cudaFuncAttributeMaxDynamicSharedMemorySize, SMEM_BYTES);

    lstm_mma_kernel<<<NCTA, NTHR, SMEM_BYTES>>>(xin, Wih, Whh, bih, bhh,
                                                Wdec, bdec, out);
    (void)in_sizes; (void)n_in; (void)out_size;
}